// round 12
// baseline (speedup 1.0000x reference)
#include <cuda_runtime.h>
#include <cuda_bf16.h>
#include <stdint.h>
#include <math.h>

// Problem sizes (fixed)
#define BB   64
#define TT   512
#define EE   1024
#define HH   1024
#define NG   4096
#define AF_ELEMS (64ULL*512ULL*1024ULL)
#define NCTA 128

typedef unsigned long long u64;
typedef unsigned int u32;

// Static device scratch (allocation-free)
__device__ float g_gx[(size_t)TT * BB * NG];        // 512 MB: GX[t][b][n]
__device__ __nv_bfloat16 g_abf[2][2][BB][HH];       // a state bf16 hi/lo, par-buffered
__device__ u32   g_bar[TT];                         // monotonic barrier counters
__device__ u32   g_bar_pro;                         // prologue barrier counter
__device__ __nv_bfloat16 g_xhi[(size_t)BB*TT*EE];   // 64 MB
__device__ __nv_bfloat16 g_xlo[(size_t)BB*TT*EE];   // 64 MB
__device__ __nv_bfloat16 g_whi[(size_t)NG*HH];      // 8 MB   [g*1024+n][k]
__device__ __nv_bfloat16 g_wlo[(size_t)NG*HH];      // 8 MB

__device__ __forceinline__ float sigf(float x) { return 1.0f / (1.0f + expf(-x)); }
__device__ __forceinline__ u32 smem_u32(const void* p) {
    u32 a; asm("{ .reg .u64 t; cvta.to.shared.u64 t, %1; cvt.u32.u64 %0, t; }"
               : "=r"(a) : "l"(p));
    return a;
}
__device__ __forceinline__ u32 pkbf2(__nv_bfloat16 a, __nv_bfloat16 b) {
    __nv_bfloat162 t; t.x = a; t.y = b;
    return *(u32*)&t;
}
#define STS128(a, x, y, z, w) asm volatile("st.shared.v4.b32 [%0], {%1,%2,%3,%4};" :: "r"(a), "r"(x), "r"(y), "r"(z), "r"(w) : "memory")
#define LDM4(d, a) asm volatile("ldmatrix.sync.aligned.m8n8.x4.shared.b16 {%0,%1,%2,%3}, [%4];" \
    : "=r"((d)[0]), "=r"((d)[1]), "=r"((d)[2]), "=r"((d)[3]) : "r"(a))
#define MMA16816(c, a, b0v, b1v) asm volatile( \
    "mma.sync.aligned.m16n8k16.row.col.f32.bf16.bf16.f32 " \
    "{%0,%1,%2,%3}, {%4,%5,%6,%7}, {%8,%9}, {%0,%1,%2,%3};" \
    : "+f"((c)[0]), "+f"((c)[1]), "+f"((c)[2]), "+f"((c)[3]) \
    : "r"((a)[0]), "r"((a)[1]), "r"((a)[2]), "r"((a)[3]), "r"(b0v), "r"(b1v))
#define CPASYNC16(d, s) asm volatile("cp.async.cg.shared.global [%0], [%1], 16;" :: "r"(d), "l"(s) : "memory")
#define CPCOMMIT()      asm volatile("cp.async.commit_group;" ::: "memory")
#define CPWAIT(n)       asm volatile("cp.async.wait_group %0;" :: "n"(n) : "memory")

// ---------------------------------------------------------------------------
// Split kernel (validated R9): fp32 -> (bf16 hi, bf16 lo) for X and x-part W.
// ---------------------------------------------------------------------------
#define NX4 8388608
#define NW4 1048576

__global__ __launch_bounds__(256) void split_kernel(
    const float* __restrict__ x,
    const float* __restrict__ wc, const float* __restrict__ wu,
    const float* __restrict__ wf, const float* __restrict__ wo)
{
    const size_t i = (size_t)blockIdx.x * 256 + threadIdx.x;
    const float* src;
    __nv_bfloat162* dh;
    __nv_bfloat162* dl;
    if (i < NX4) {
        src = x + i * 4;
        dh = ((__nv_bfloat162*)g_xhi) + i * 2;
        dl = ((__nv_bfloat162*)g_xlo) + i * 2;
    } else if (i < NX4 + NW4) {
        const size_t j = i - NX4;
        const size_t e = j * 4;
        const int ng = (int)(e >> 10), k = (int)(e & 1023);
        const int g = ng >> 10, n = ng & 1023;
        const float* wg = (g == 0) ? wc : (g == 1) ? wu : (g == 2) ? wf : wo;
        src = wg + (size_t)n * 2048 + 1024 + k;
        dh = ((__nv_bfloat162*)g_whi) + j * 2;
        dl = ((__nv_bfloat162*)g_wlo) + j * 2;
    } else return;

    const float4 v = *(const float4*)src;
    __nv_bfloat16 h0 = __float2bfloat16_rn(v.x);
    __nv_bfloat16 h1 = __float2bfloat16_rn(v.y);
    __nv_bfloat16 h2 = __float2bfloat16_rn(v.z);
    __nv_bfloat16 h3 = __float2bfloat16_rn(v.w);
    __nv_bfloat16 l0 = __float2bfloat16_rn(v.x - __bfloat162float(h0));
    __nv_bfloat16 l1 = __float2bfloat16_rn(v.y - __bfloat162float(h1));
    __nv_bfloat16 l2 = __float2bfloat16_rn(v.z - __bfloat162float(h2));
    __nv_bfloat16 l3 = __float2bfloat16_rn(v.w - __bfloat162float(h3));
    __nv_bfloat162 p;
    p.x = h0; p.y = h1; dh[0] = p;
    p.x = h2; p.y = h3; dh[1] = p;
    p.x = l0; p.y = l1; dl[0] = p;
    p.x = l2; p.y = l3; dl[1] = p;
}

// ---------------------------------------------------------------------------
// Phase 1 (validated R9): split-bf16 GEMM via mma.sync.
// ---------------------------------------------------------------------------
__global__ __launch_bounds__(256) void gx_mma(
    const float* __restrict__ bc, const float* __restrict__ bu,
    const float* __restrict__ bf, const float* __restrict__ bo)
{
    __shared__ __align__(16) __nv_bfloat16 sAh[128 * 40];
    __shared__ __align__(16) __nv_bfloat16 sAl[128 * 40];
    __shared__ __align__(16) __nv_bfloat16 sBh[128 * 40];
    __shared__ __align__(16) __nv_bfloat16 sBl[128 * 40];
    __shared__ float s_bias[128];

    const int tid = threadIdx.x, lane = tid & 31, wid = tid >> 5;
    const int nbase = blockIdx.x * 128;
    const int mbase = blockIdx.y * 128;
    const int wm = (wid >> 2) * 64;
    const int wn = (wid & 3) * 32;
    const int q = lane >> 3, r8 = lane & 7;

    if (tid < 128) {
        const int g = nbase >> 10;
        const float* bg = (g == 0) ? bc : (g == 1) ? bu : (g == 2) ? bf : bo;
        s_bias[tid] = bg[(nbase & 1023) + tid];
    }

    const u32 aAh = smem_u32(sAh), aAl = smem_u32(sAl);
    const u32 aBh = smem_u32(sBh), aBl = smem_u32(sBl);
    const u32 arb = (u32)((wm + (q & 1) * 8 + r8) * 80 + (q >> 1) * 16);
    const u32 brb = (u32)((wn + (q >> 1) * 8 + r8) * 80 + (q & 1) * 16);

    const int lrow = tid >> 2, lkq = tid & 3;
    const __nv_bfloat16* pAh = g_xhi + (size_t)(mbase + lrow) * 1024 + lkq * 8;
    const __nv_bfloat16* pAl = g_xlo + (size_t)(mbase + lrow) * 1024 + lkq * 8;
    const __nv_bfloat16* pBh = g_whi + (size_t)(nbase + lrow) * 1024 + lkq * 8;
    const __nv_bfloat16* pBl = g_wlo + (size_t)(nbase + lrow) * 1024 + lkq * 8;
    const u32 sso = (u32)(lrow * 80 + lkq * 16);

    float C[4][4][4];
    #pragma unroll
    for (int mf = 0; mf < 4; mf++)
        #pragma unroll
        for (int nf = 0; nf < 4; nf++)
            #pragma unroll
            for (int e = 0; e < 4; e++) C[mf][nf][e] = 0.0f;

    for (int k0 = 0; k0 < 1024; k0 += 32) {
        const uint4 va0 = *(const uint4*)(pAh + k0);
        const uint4 va1 = *(const uint4*)(pAh + 64 * 1024 + k0);
        const uint4 va2 = *(const uint4*)(pAl + k0);
        const uint4 va3 = *(const uint4*)(pAl + 64 * 1024 + k0);
        const uint4 vb0 = *(const uint4*)(pBh + k0);
        const uint4 vb1 = *(const uint4*)(pBh + 64 * 1024 + k0);
        const uint4 vb2 = *(const uint4*)(pBl + k0);
        const uint4 vb3 = *(const uint4*)(pBl + 64 * 1024 + k0);
        __syncthreads();
        STS128(aAh + sso,        va0.x, va0.y, va0.z, va0.w);
        STS128(aAh + sso + 5120, va1.x, va1.y, va1.z, va1.w);
        STS128(aAl + sso,        va2.x, va2.y, va2.z, va2.w);
        STS128(aAl + sso + 5120, va3.x, va3.y, va3.z, va3.w);
        STS128(aBh + sso,        vb0.x, vb0.y, vb0.z, vb0.w);
        STS128(aBh + sso + 5120, vb1.x, vb1.y, vb1.z, vb1.w);
        STS128(aBl + sso,        vb2.x, vb2.y, vb2.z, vb2.w);
        STS128(aBl + sso + 5120, vb3.x, vb3.y, vb3.z, vb3.w);
        __syncthreads();

        #pragma unroll
        for (int ks = 0; ks < 2; ks++) {
            u32 ah[4][4], al[4][4], bh[2][4], bl[2][4];
            #pragma unroll
            for (int mf = 0; mf < 4; mf++) {
                LDM4(ah[mf], aAh + arb + mf * 1280 + ks * 32);
                LDM4(al[mf], aAl + arb + mf * 1280 + ks * 32);
            }
            #pragma unroll
            for (int bg = 0; bg < 2; bg++) {
                LDM4(bh[bg], aBh + brb + bg * 1280 + ks * 32);
                LDM4(bl[bg], aBl + brb + bg * 1280 + ks * 32);
            }
            #pragma unroll
            for (int mf = 0; mf < 4; mf++)
                #pragma unroll
                for (int nf = 0; nf < 4; nf++) {
                    const int bg = nf >> 1, o = (nf & 1) * 2;
                    MMA16816(C[mf][nf], ah[mf], bh[bg][o], bh[bg][o + 1]);
                    MMA16816(C[mf][nf], ah[mf], bl[bg][o], bl[bg][o + 1]);
                    MMA16816(C[mf][nf], al[mf], bh[bg][o], bh[bg][o + 1]);
                }
        }
    }

    const int g2 = lane >> 2, t2 = lane & 3;
    #pragma unroll
    for (int mf = 0; mf < 4; mf++) {
        const int m0 = mbase + wm + mf * 16 + g2;
        const int b  = m0 >> 9;
        const int t0 = m0 & 511;
        #pragma unroll
        for (int nf = 0; nf < 4; nf++) {
            const int nloc = wn + nf * 8 + t2 * 2;
            float2 v0, v1;
            v0.x = C[mf][nf][0] + s_bias[nloc];
            v0.y = C[mf][nf][1] + s_bias[nloc + 1];
            v1.x = C[mf][nf][2] + s_bias[nloc];
            v1.y = C[mf][nf][3] + s_bias[nloc + 1];
            *(float2*)(g_gx + ((size_t)t0 * BB + b) * NG + nbase + nloc) = v0;
            *(float2*)(g_gx + ((size_t)(t0 + 8) * BB + b) * NG + nbase + nloc) = v1;
        }
    }
}

// ---------------------------------------------------------------------------
// Phase 2: PERSISTENT recurrence with mma.sync (split bf16, 3 terms).
//   R11 core + this round: cp.async a-staging (no LDG->reg->STS round trip),
//   3 independent accumulator sets (breaks HMMA RAW chains), GX prefetched
//   into registers during the PREVIOUS step's grid barrier.
// SMEM bytes:
//   [0,66048)        W hi  (32 x 2064)
//   [66048,132096)   W lo
//   [132096,201728)  a bufs: [chunkpar][split] 4 x 64x272
//   [201728,210432)  pre[64][34] f32
//   [210432,218880)  gx [64][33] f32
// ---------------------------------------------------------------------------
#define OFF_WHI 0
#define OFF_WLO 66048
#define OFF_A   132096
#define OFF_PRE 201728
#define OFF_GX  210432
#define SMEM_BYTES 218880
#define ABUFB(cp, sp) (OFF_A + (cp) * 34816 + (sp) * 17408)

__global__ __launch_bounds__(256, 1) void lstm_persist(
    const float* __restrict__ a0, const float* __restrict__ c0,
    const float* __restrict__ wc, const float* __restrict__ wu,
    const float* __restrict__ wf, const float* __restrict__ wo,
    float* __restrict__ out)
{
    extern __shared__ __align__(16) char smc[];
    const u32 sb = smem_u32(smc);
    float* pre_s = (float*)(smc + OFF_PRE);
    float* gx_s  = (float*)(smc + OFF_GX);

    const int tid = threadIdx.x, lane = tid & 31, wid = tid >> 5;
    const int mw = wid & 3, nw = wid >> 2;
    const int hbase = blockIdx.x * 8;

    // ---- prologue: weights -> SMEM bf16 hi/lo (recurrent cols [0,1024)) ----
    #pragma unroll 4
    for (int v = 0; v < 32; v++) {
        const int idx = tid + v * 256;
        const int r = idx >> 8, kq = idx & 255;
        const int g = r >> 3, hh = r & 7;
        const float* wsel = (g == 0) ? wc : (g == 1) ? wu : (g == 2) ? wf : wo;
        const float4 w = *(const float4*)(wsel + (size_t)(hbase + hh) * 2048 + kq * 4);
        __nv_bfloat16 h0 = __float2bfloat16_rn(w.x);
        __nv_bfloat16 h1 = __float2bfloat16_rn(w.y);
        __nv_bfloat16 h2 = __float2bfloat16_rn(w.z);
        __nv_bfloat16 h3 = __float2bfloat16_rn(w.w);
        __nv_bfloat16 l0 = __float2bfloat16_rn(w.x - __bfloat162float(h0));
        __nv_bfloat16 l1 = __float2bfloat16_rn(w.y - __bfloat162float(h1));
        __nv_bfloat16 l2 = __float2bfloat16_rn(w.z - __bfloat162float(h2));
        __nv_bfloat16 l3 = __float2bfloat16_rn(w.w - __bfloat162float(h3));
        u32* ph = (u32*)(smc + OFF_WHI + r * 2064 + kq * 8);
        u32* pl = (u32*)(smc + OFF_WLO + r * 2064 + kq * 8);
        ph[0] = pkbf2(h0, h1); ph[1] = pkbf2(h2, h3);
        pl[0] = pkbf2(l0, l1); pl[1] = pkbf2(l2, l3);
    }

    // ---- prologue: this CTA's slice of a0 -> g_abf[0] hi/lo ----
    {
        const int idx = blockIdx.x * 512 + tid * 2;
        const int b = idx >> 10, h = idx & 1023;
        const float2 v = *(const float2*)(a0 + (size_t)b * 1024 + h);
        __nv_bfloat16 h0 = __float2bfloat16_rn(v.x);
        __nv_bfloat16 h1 = __float2bfloat16_rn(v.y);
        __nv_bfloat16 l0 = __float2bfloat16_rn(v.x - __bfloat162float(h0));
        __nv_bfloat16 l1 = __float2bfloat16_rn(v.y - __bfloat162float(h1));
        *(u32*)&g_abf[0][0][b][h] = pkbf2(h0, h1);
        *(u32*)&g_abf[0][1][b][h] = pkbf2(l0, l1);
    }

    // ---- c-state in registers: thread owns (b_e, 2 h values) ----
    const int b_e = tid & 63, jp = tid >> 6;
    const int h0e = hbase + jp * 2;
    float creg[2];
    creg[0] = c0[b_e * HH + h0e];
    creg[1] = c0[b_e * HH + h0e + 1];

    // ---- prologue grid barrier (monotonic) ----
    __threadfence();
    __syncthreads();
    if (tid == 0) {
        const u32 old = atomicAdd(&g_bar_pro, 1u);
        const u32 target = (old & ~127u) + 128u;
        while (*(volatile u32*)&g_bar_pro < target) { }
        __threadfence();
    }
    __syncthreads();

    // ldmatrix per-lane bases
    const int q = lane >> 3, r8 = lane & 7;
    const u32 a_off = (u32)((mw * 16 + (q & 1) * 8 + r8) * 272 + (q >> 1) * 16);
    const u32 b_off = (u32)((nw * 16 + (q >> 1) * 8 + r8) * 2064 + (q & 1) * 16);

    // staging mappings (hoisted)
    const int sgb = tid >> 2, sgg = tid & 3;
    const float* gx_src0 = g_gx + (size_t)sgb * NG + sgg * 1024 + hbase;
    int abb[8], akk[8], asp[8];
    #pragma unroll
    for (int v = 0; v < 8; v++) {
        const int sp = v >> 2, idx2 = tid + (v & 3) * 256;
        asp[v] = sp; abb[v] = idx2 >> 4; akk[v] = idx2 & 15;
    }

    // GX prefetch for t = 0
    float4 gxr0 = __ldcs((const float4*)gx_src0);
    float4 gxr1 = __ldcs((const float4*)(gx_src0 + 4));

    for (int t = 0; t < TT; t++) {
        const int par = t & 1;
        const __nv_bfloat16* abase = &g_abf[par][0][0][0];

        // ---- prologue staging: cp.async chunks 0 and 1 ----
        #pragma unroll
        for (int v = 0; v < 8; v++)
            CPASYNC16(sb + ABUFB(0, asp[v]) + abb[v] * 272 + akk[v] * 16,
                      (const void*)(abase + asp[v] * 65536 + abb[v] * 1024 + akk[v] * 8));
        CPCOMMIT();
        #pragma unroll
        for (int v = 0; v < 8; v++)
            CPASYNC16(sb + ABUFB(1, asp[v]) + abb[v] * 272 + akk[v] * 16,
                      (const void*)(abase + asp[v] * 65536 + abb[v] * 1024 + 128 + akk[v] * 8));
        CPCOMMIT();
        CPWAIT(1);
        __syncthreads();

        float Ca[2][4], Cb[2][4], Cc[2][4];   // hh, hl, lh terms
        #pragma unroll
        for (int nf = 0; nf < 2; nf++)
            #pragma unroll
            for (int e = 0; e < 4; e++) { Ca[nf][e] = 0.0f; Cb[nf][e] = 0.0f; Cc[nf][e] = 0.0f; }

        for (int i = 0; i < 8; i++) {
            // compute chunk i on buffer i&1
            const u32 ahB = sb + ABUFB(i & 1, 0) + a_off;
            const u32 alB = sb + ABUFB(i & 1, 1) + a_off;
            const u32 bhB = sb + OFF_WHI + b_off + i * 256;
            const u32 blB = sb + OFF_WLO + b_off + i * 256;
            #pragma unroll
            for (int k16 = 0; k16 < 8; k16++) {
                u32 ah[4], al[4], bh[4], bl[4];
                LDM4(ah, ahB + k16 * 32);
                LDM4(al, alB + k16 * 32);
                LDM4(bh, bhB + k16 * 32);
                LDM4(bl, blB + k16 * 32);
                #pragma unroll
                for (int nf = 0; nf < 2; nf++) {
                    const int o = nf * 2;
                    MMA16816(Ca[nf], ah, bh[o], bh[o + 1]);
                    MMA16816(Cb[nf], ah, bl[o], bl[o + 1]);
                    MMA16816(Cc[nf], al, bh[o], bh[o + 1]);
                }
            }
            if (i < 7) {
                CPWAIT(0);        // chunk i+1 landed
                __syncthreads();  // all warps done with buffer i&1 + visibility
                if (i < 6) {      // prefetch chunk i+2 into buffer i&1
                    #pragma unroll
                    for (int v = 0; v < 8; v++)
                        CPASYNC16(sb + ABUFB(i & 1, asp[v]) + abb[v] * 272 + akk[v] * 16,
                                  (const void*)(abase + asp[v] * 65536 + abb[v] * 1024
                                                + (i + 2) * 128 + akk[v] * 8));
                    CPCOMMIT();
                }
            }
        }

        // ---- fragments -> pre_s[b][r] (combine 3 terms); gx regs -> gx_s ----
        {
            const int g2 = lane >> 2, t2 = lane & 3;
            const int row0 = mw * 16 + g2;
            #pragma unroll
            for (int nf = 0; nf < 2; nf++) {
                const int col = nw * 16 + nf * 8 + t2 * 2;
                float2 v0, v1;
                v0.x = Ca[nf][0] + Cb[nf][0] + Cc[nf][0];
                v0.y = Ca[nf][1] + Cb[nf][1] + Cc[nf][1];
                v1.x = Ca[nf][2] + Cb[nf][2] + Cc[nf][2];
                v1.y = Ca[nf][3] + Cb[nf][3] + Cc[nf][3];
                *(float2*)&pre_s[row0 * 34 + col] = v0;
                *(float2*)&pre_s[(row0 + 8) * 34 + col] = v1;
            }
            float* dst = gx_s + sgb * 33 + sgg * 8;
            dst[0] = gxr0.x; dst[1] = gxr0.y; dst[2] = gxr0.z; dst[3] = gxr0.w;
            dst[4] = gxr1.x; dst[5] = gxr1.y; dst[6] = gxr1.z; dst[7] = gxr1.w;
        }
        __syncthreads();

        // ---- elementwise LSTM update: thread owns (b_e, h0e..h0e+1) ----
        float a1v[2], c1v[2];
        #pragma unroll
        for (int e = 0; e < 2; e++) {
            const int hh = jp * 2 + e;
            const float p0 = pre_s[b_e * 34 + hh]      + gx_s[b_e * 33 + hh];
            const float p1 = pre_s[b_e * 34 + 8 + hh]  + gx_s[b_e * 33 + 8 + hh];
            const float p2 = pre_s[b_e * 34 + 16 + hh] + gx_s[b_e * 33 + 16 + hh];
            const float p3 = pre_s[b_e * 34 + 24 + hh] + gx_s[b_e * 33 + 24 + hh];
            const float cand = tanhf(p0);
            const float gu   = sigf(p1);
            const float gf   = sigf(p2);
            const float go   = sigf(p3);
            const float cc   = gu * cand + gf * creg[e];
            creg[e] = cc;
            c1v[e] = cc;
            a1v[e] = go * tanhf(cc);
        }
        {
            float2 av; av.x = a1v[0]; av.y = a1v[1];
            *(float2*)(out + (size_t)b_e * (TT * HH) + (size_t)t * HH + h0e) = av;
            __nv_bfloat16 h0 = __float2bfloat16_rn(a1v[0]);
            __nv_bfloat16 h1 = __float2bfloat16_rn(a1v[1]);
            __nv_bfloat16 l0 = __float2bfloat16_rn(a1v[0] - __bfloat162float(h0));
            __nv_bfloat16 l1 = __float2bfloat16_rn(a1v[1] - __bfloat162float(h1));
            const int np = (t + 1) & 1;
            *(u32*)&g_abf[np][0][b_e][h0e] = pkbf2(h0, h1);
            *(u32*)&g_abf[np][1][b_e][h0e] = pkbf2(l0, l1);
            if (t == TT - 1) {
                *(float2*)(out + AF_ELEMS + (size_t)b_e * HH + h0e) = av;
                float2 cv; cv.x = c1v[0]; cv.y = c1v[1];
                *(float2*)(out + AF_ELEMS + (size_t)BB * HH + (size_t)b_e * HH + h0e) = cv;
            }
        }

        // ---- grid barrier (monotonic); GX(t+1) prefetch hides under it ----
        if (t < TT - 1) {
            gxr0 = __ldcs((const float4*)(gx_src0 + (size_t)(t + 1) * BB * NG));
            gxr1 = __ldcs((const float4*)(gx_src0 + (size_t)(t + 1) * BB * NG + 4));
            __threadfence();
            __syncthreads();
            if (tid == 0) {
                const u32 old = atomicAdd(&g_bar[t], 1u);
                const u32 target = (old & ~127u) + 128u;
                while (*(volatile u32*)&g_bar[t] < target) { }
                __threadfence();
            }
            __syncthreads();
        }
    }
}

// Tiny dummy kernel: shifts ncu's captured launch slot so the NEXT profile
// lands on lstm_persist instead of split_kernel. Deterministic, no memory.
__global__ void dummy_k() {}

// ---------------------------------------------------------------------------
extern "C" void kernel_launch(void* const* d_in, const int* in_sizes, int n_in,
                              void* d_out, int out_size) {
    (void)in_sizes; (void)n_in; (void)out_size;
    const float* x  = (const float*)d_in[0];
    const float* a0 = (const float*)d_in[1];
    const float* c0 = (const float*)d_in[2];
    const float* wc = (const float*)d_in[3];
    const float* wu = (const float*)d_in[4];
    const float* wf = (const float*)d_in[5];
    const float* wo = (const float*)d_in[6];
    const float* bc = (const float*)d_in[7];
    const float* bu = (const float*)d_in[8];
    const float* bf = (const float*)d_in[9];
    const float* bo = (const float*)d_in[10];
    float* out = (float*)d_out;

    static int attr_set = 0;
    if (!attr_set) {
        cudaFuncSetAttribute(lstm_persist,
                             cudaFuncAttributeMaxDynamicSharedMemorySize,
                             SMEM_BYTES);
        attr_set = 1;
    }

    // Phase 0: split fp32 -> bf16 hi/lo
    split_kernel<<<(NX4 + NW4 + 255) / 256, 256>>>(x, wc, wu, wf, wo);

    // Phase 1: HMMA x-projection (GX)
    dim3 g1(32, 256);
    gx_mma<<<g1, 256>>>(bc, bu, bf, bo);

    // Phase 2: persistent tensor-core recurrence
    lstm_persist<<<NCTA, 256, SMEM_BYTES>>>(a0, c0, wc, wu, wf, wo, out);

    // Launch-slot shim for ncu alignment (negligible cost)
    dummy_k<<<1, 32>>>();
}

// round 13
// speedup vs baseline: 1.4092x; 1.4092x over previous
#include <cuda_runtime.h>
#include <cuda_bf16.h>
#include <stdint.h>
#include <math.h>

// Problem sizes (fixed)
#define BB   64
#define TT   512
#define EE   1024
#define HH   1024
#define NG   4096
#define AF_ELEMS (64ULL*512ULL*1024ULL)
#define NCTA 128

typedef unsigned long long u64;
typedef unsigned int u32;

// Static device scratch (allocation-free)
__device__ float g_gx[(size_t)TT * BB * NG];        // 512 MB: GX[t][b][n]
__device__ __nv_bfloat16 g_abf[2][2][BB][HH];       // a state bf16 hi/lo, par-buffered
__device__ u32   g_bar[TT];                         // monotonic barrier counters
__device__ u32   g_bar_pro;                         // prologue barrier counter
__device__ __nv_bfloat16 g_xhi[(size_t)BB*TT*EE];   // 64 MB
__device__ __nv_bfloat16 g_xlo[(size_t)BB*TT*EE];   // 64 MB
__device__ __nv_bfloat16 g_whi[(size_t)NG*HH];      // 8 MB   [g*1024+n][k]
__device__ __nv_bfloat16 g_wlo[(size_t)NG*HH];      // 8 MB

__device__ __forceinline__ float sigf(float x) { return 1.0f / (1.0f + expf(-x)); }
__device__ __forceinline__ u32 smem_u32(const void* p) {
    u32 a; asm("{ .reg .u64 t; cvta.to.shared.u64 t, %1; cvt.u32.u64 %0, t; }"
               : "=r"(a) : "l"(p));
    return a;
}
__device__ __forceinline__ u32 pkbf2(__nv_bfloat16 a, __nv_bfloat16 b) {
    __nv_bfloat162 t; t.x = a; t.y = b;
    return *(u32*)&t;
}
#define STS128(a, x, y, z, w) asm volatile("st.shared.v4.b32 [%0], {%1,%2,%3,%4};" :: "r"(a), "r"(x), "r"(y), "r"(z), "r"(w) : "memory")
#define LDM4(d, a) asm volatile("ldmatrix.sync.aligned.m8n8.x4.shared.b16 {%0,%1,%2,%3}, [%4];" \
    : "=r"((d)[0]), "=r"((d)[1]), "=r"((d)[2]), "=r"((d)[3]) : "r"(a))
#define MMA16816(c, a, b0v, b1v) asm volatile( \
    "mma.sync.aligned.m16n8k16.row.col.f32.bf16.bf16.f32 " \
    "{%0,%1,%2,%3}, {%4,%5,%6,%7}, {%8,%9}, {%0,%1,%2,%3};" \
    : "+f"((c)[0]), "+f"((c)[1]), "+f"((c)[2]), "+f"((c)[3]) \
    : "r"((a)[0]), "r"((a)[1]), "r"((a)[2]), "r"((a)[3]), "r"(b0v), "r"(b1v))

// ---------------------------------------------------------------------------
// Split kernel (validated R9): fp32 -> (bf16 hi, bf16 lo) for X and x-part W.
// ---------------------------------------------------------------------------
#define NX4 8388608
#define NW4 1048576

__global__ __launch_bounds__(256) void split_kernel(
    const float* __restrict__ x,
    const float* __restrict__ wc, const float* __restrict__ wu,
    const float* __restrict__ wf, const float* __restrict__ wo)
{
    const size_t i = (size_t)blockIdx.x * 256 + threadIdx.x;
    const float* src;
    __nv_bfloat162* dh;
    __nv_bfloat162* dl;
    if (i < NX4) {
        src = x + i * 4;
        dh = ((__nv_bfloat162*)g_xhi) + i * 2;
        dl = ((__nv_bfloat162*)g_xlo) + i * 2;
    } else if (i < NX4 + NW4) {
        const size_t j = i - NX4;
        const size_t e = j * 4;
        const int ng = (int)(e >> 10), k = (int)(e & 1023);
        const int g = ng >> 10, n = ng & 1023;
        const float* wg = (g == 0) ? wc : (g == 1) ? wu : (g == 2) ? wf : wo;
        src = wg + (size_t)n * 2048 + 1024 + k;
        dh = ((__nv_bfloat162*)g_whi) + j * 2;
        dl = ((__nv_bfloat162*)g_wlo) + j * 2;
    } else return;

    const float4 v = *(const float4*)src;
    __nv_bfloat16 h0 = __float2bfloat16_rn(v.x);
    __nv_bfloat16 h1 = __float2bfloat16_rn(v.y);
    __nv_bfloat16 h2 = __float2bfloat16_rn(v.z);
    __nv_bfloat16 h3 = __float2bfloat16_rn(v.w);
    __nv_bfloat16 l0 = __float2bfloat16_rn(v.x - __bfloat162float(h0));
    __nv_bfloat16 l1 = __float2bfloat16_rn(v.y - __bfloat162float(h1));
    __nv_bfloat16 l2 = __float2bfloat16_rn(v.z - __bfloat162float(h2));
    __nv_bfloat16 l3 = __float2bfloat16_rn(v.w - __bfloat162float(h3));
    __nv_bfloat162 p;
    p.x = h0; p.y = h1; dh[0] = p;
    p.x = h2; p.y = h3; dh[1] = p;
    p.x = l0; p.y = l1; dl[0] = p;
    p.x = l2; p.y = l3; dl[1] = p;
}

// ---------------------------------------------------------------------------
// Phase 1 (validated R9): split-bf16 GEMM via mma.sync.
// ---------------------------------------------------------------------------
__global__ __launch_bounds__(256) void gx_mma(
    const float* __restrict__ bc, const float* __restrict__ bu,
    const float* __restrict__ bf, const float* __restrict__ bo)
{
    __shared__ __align__(16) __nv_bfloat16 sAh[128 * 40];
    __shared__ __align__(16) __nv_bfloat16 sAl[128 * 40];
    __shared__ __align__(16) __nv_bfloat16 sBh[128 * 40];
    __shared__ __align__(16) __nv_bfloat16 sBl[128 * 40];
    __shared__ float s_bias[128];

    const int tid = threadIdx.x, lane = tid & 31, wid = tid >> 5;
    const int nbase = blockIdx.x * 128;
    const int mbase = blockIdx.y * 128;
    const int wm = (wid >> 2) * 64;
    const int wn = (wid & 3) * 32;
    const int q = lane >> 3, r8 = lane & 7;

    if (tid < 128) {
        const int g = nbase >> 10;
        const float* bg = (g == 0) ? bc : (g == 1) ? bu : (g == 2) ? bf : bo;
        s_bias[tid] = bg[(nbase & 1023) + tid];
    }

    const u32 aAh = smem_u32(sAh), aAl = smem_u32(sAl);
    const u32 aBh = smem_u32(sBh), aBl = smem_u32(sBl);
    const u32 arb = (u32)((wm + (q & 1) * 8 + r8) * 80 + (q >> 1) * 16);
    const u32 brb = (u32)((wn + (q >> 1) * 8 + r8) * 80 + (q & 1) * 16);

    const int lrow = tid >> 2, lkq = tid & 3;
    const __nv_bfloat16* pAh = g_xhi + (size_t)(mbase + lrow) * 1024 + lkq * 8;
    const __nv_bfloat16* pAl = g_xlo + (size_t)(mbase + lrow) * 1024 + lkq * 8;
    const __nv_bfloat16* pBh = g_whi + (size_t)(nbase + lrow) * 1024 + lkq * 8;
    const __nv_bfloat16* pBl = g_wlo + (size_t)(nbase + lrow) * 1024 + lkq * 8;
    const u32 sso = (u32)(lrow * 80 + lkq * 16);

    float C[4][4][4];
    #pragma unroll
    for (int mf = 0; mf < 4; mf++)
        #pragma unroll
        for (int nf = 0; nf < 4; nf++)
            #pragma unroll
            for (int e = 0; e < 4; e++) C[mf][nf][e] = 0.0f;

    for (int k0 = 0; k0 < 1024; k0 += 32) {
        const uint4 va0 = *(const uint4*)(pAh + k0);
        const uint4 va1 = *(const uint4*)(pAh + 64 * 1024 + k0);
        const uint4 va2 = *(const uint4*)(pAl + k0);
        const uint4 va3 = *(const uint4*)(pAl + 64 * 1024 + k0);
        const uint4 vb0 = *(const uint4*)(pBh + k0);
        const uint4 vb1 = *(const uint4*)(pBh + 64 * 1024 + k0);
        const uint4 vb2 = *(const uint4*)(pBl + k0);
        const uint4 vb3 = *(const uint4*)(pBl + 64 * 1024 + k0);
        __syncthreads();
        STS128(aAh + sso,        va0.x, va0.y, va0.z, va0.w);
        STS128(aAh + sso + 5120, va1.x, va1.y, va1.z, va1.w);
        STS128(aAl + sso,        va2.x, va2.y, va2.z, va2.w);
        STS128(aAl + sso + 5120, va3.x, va3.y, va3.z, va3.w);
        STS128(aBh + sso,        vb0.x, vb0.y, vb0.z, vb0.w);
        STS128(aBh + sso + 5120, vb1.x, vb1.y, vb1.z, vb1.w);
        STS128(aBl + sso,        vb2.x, vb2.y, vb2.z, vb2.w);
        STS128(aBl + sso + 5120, vb3.x, vb3.y, vb3.z, vb3.w);
        __syncthreads();

        #pragma unroll
        for (int ks = 0; ks < 2; ks++) {
            u32 ah[4][4], al[4][4], bh[2][4], bl[2][4];
            #pragma unroll
            for (int mf = 0; mf < 4; mf++) {
                LDM4(ah[mf], aAh + arb + mf * 1280 + ks * 32);
                LDM4(al[mf], aAl + arb + mf * 1280 + ks * 32);
            }
            #pragma unroll
            for (int bg = 0; bg < 2; bg++) {
                LDM4(bh[bg], aBh + brb + bg * 1280 + ks * 32);
                LDM4(bl[bg], aBl + brb + bg * 1280 + ks * 32);
            }
            #pragma unroll
            for (int mf = 0; mf < 4; mf++)
                #pragma unroll
                for (int nf = 0; nf < 4; nf++) {
                    const int bg = nf >> 1, o = (nf & 1) * 2;
                    MMA16816(C[mf][nf], ah[mf], bh[bg][o], bh[bg][o + 1]);
                    MMA16816(C[mf][nf], ah[mf], bl[bg][o], bl[bg][o + 1]);
                    MMA16816(C[mf][nf], al[mf], bh[bg][o], bh[bg][o + 1]);
                }
        }
    }

    const int g2 = lane >> 2, t2 = lane & 3;
    #pragma unroll
    for (int mf = 0; mf < 4; mf++) {
        const int m0 = mbase + wm + mf * 16 + g2;
        const int b  = m0 >> 9;
        const int t0 = m0 & 511;
        #pragma unroll
        for (int nf = 0; nf < 4; nf++) {
            const int nloc = wn + nf * 8 + t2 * 2;
            float2 v0, v1;
            v0.x = C[mf][nf][0] + s_bias[nloc];
            v0.y = C[mf][nf][1] + s_bias[nloc + 1];
            v1.x = C[mf][nf][2] + s_bias[nloc];
            v1.y = C[mf][nf][3] + s_bias[nloc + 1];
            *(float2*)(g_gx + ((size_t)t0 * BB + b) * NG + nbase + nloc) = v0;
            *(float2*)(g_gx + ((size_t)(t0 + 8) * BB + b) * NG + nbase + nloc) = v1;
        }
    }
}

// ---------------------------------------------------------------------------
// Phase 2: PERSISTENT recurrence with mma.sync (split bf16, 3 terms).
//   R11's validated deep-slack LDG->reg->STS staging (cp.async reverted)
//   + R12's 3 independent accumulator sets (breaks 24-deep HMMA RAW chains)
//   + GX prefetched into registers during the PREVIOUS step's grid barrier.
// SMEM bytes:
//   [0,66048)        W hi  (32 x 2064)
//   [66048,132096)   W lo
//   [132096,201728)  a bufs: [chunkpar][split] 4 x 64x272
//   [201728,210432)  pre[64][34] f32
//   [210432,218880)  gx [64][33] f32
// ---------------------------------------------------------------------------
#define OFF_WHI 0
#define OFF_WLO 66048
#define OFF_A   132096
#define OFF_PRE 201728
#define OFF_GX  210432
#define SMEM_BYTES 218880
#define ABUFB(cp, sp) (OFF_A + (cp) * 34816 + (sp) * 17408)

__global__ __launch_bounds__(256, 1) void lstm_persist(
    const float* __restrict__ a0, const float* __restrict__ c0,
    const float* __restrict__ wc, const float* __restrict__ wu,
    const float* __restrict__ wf, const float* __restrict__ wo,
    float* __restrict__ out)
{
    extern __shared__ __align__(16) char smc[];
    const u32 sb = smem_u32(smc);
    float* pre_s = (float*)(smc + OFF_PRE);
    float* gx_s  = (float*)(smc + OFF_GX);

    const int tid = threadIdx.x, lane = tid & 31, wid = tid >> 5;
    const int mw = wid & 3, nw = wid >> 2;
    const int hbase = blockIdx.x * 8;

    // ---- prologue: weights -> SMEM bf16 hi/lo (recurrent cols [0,1024)) ----
    #pragma unroll 4
    for (int v = 0; v < 32; v++) {
        const int idx = tid + v * 256;
        const int r = idx >> 8, kq = idx & 255;
        const int g = r >> 3, hh = r & 7;
        const float* wsel = (g == 0) ? wc : (g == 1) ? wu : (g == 2) ? wf : wo;
        const float4 w = *(const float4*)(wsel + (size_t)(hbase + hh) * 2048 + kq * 4);
        __nv_bfloat16 h0 = __float2bfloat16_rn(w.x);
        __nv_bfloat16 h1 = __float2bfloat16_rn(w.y);
        __nv_bfloat16 h2 = __float2bfloat16_rn(w.z);
        __nv_bfloat16 h3 = __float2bfloat16_rn(w.w);
        __nv_bfloat16 l0 = __float2bfloat16_rn(w.x - __bfloat162float(h0));
        __nv_bfloat16 l1 = __float2bfloat16_rn(w.y - __bfloat162float(h1));
        __nv_bfloat16 l2 = __float2bfloat16_rn(w.z - __bfloat162float(h2));
        __nv_bfloat16 l3 = __float2bfloat16_rn(w.w - __bfloat162float(h3));
        u32* ph = (u32*)(smc + OFF_WHI + r * 2064 + kq * 8);
        u32* pl = (u32*)(smc + OFF_WLO + r * 2064 + kq * 8);
        ph[0] = pkbf2(h0, h1); ph[1] = pkbf2(h2, h3);
        pl[0] = pkbf2(l0, l1); pl[1] = pkbf2(l2, l3);
    }

    // ---- prologue: this CTA's slice of a0 -> g_abf[0] hi/lo ----
    {
        const int idx = blockIdx.x * 512 + tid * 2;
        const int b = idx >> 10, h = idx & 1023;
        const float2 v = *(const float2*)(a0 + (size_t)b * 1024 + h);
        __nv_bfloat16 h0 = __float2bfloat16_rn(v.x);
        __nv_bfloat16 h1 = __float2bfloat16_rn(v.y);
        __nv_bfloat16 l0 = __float2bfloat16_rn(v.x - __bfloat162float(h0));
        __nv_bfloat16 l1 = __float2bfloat16_rn(v.y - __bfloat162float(h1));
        *(u32*)&g_abf[0][0][b][h] = pkbf2(h0, h1);
        *(u32*)&g_abf[0][1][b][h] = pkbf2(l0, l1);
    }

    // ---- c-state in registers: thread owns (b_e, 2 h values) ----
    const int b_e = tid & 63, jp = tid >> 6;
    const int h0e = hbase + jp * 2;
    float creg[2];
    creg[0] = c0[b_e * HH + h0e];
    creg[1] = c0[b_e * HH + h0e + 1];

    // ---- prologue grid barrier (monotonic) ----
    __threadfence();
    __syncthreads();
    if (tid == 0) {
        const u32 old = atomicAdd(&g_bar_pro, 1u);
        const u32 target = (old & ~127u) + 128u;
        while (*(volatile u32*)&g_bar_pro < target) { }
        __threadfence();
    }
    __syncthreads();

    // ldmatrix per-lane bases
    const int q = lane >> 3, r8 = lane & 7;
    const u32 a_off = (u32)((mw * 16 + (q & 1) * 8 + r8) * 272 + (q >> 1) * 16);
    const u32 b_off = (u32)((nw * 16 + (q >> 1) * 8 + r8) * 2064 + (q & 1) * 16);

    // staging mappings (hoisted)
    const int sgb = tid >> 2, sgg = tid & 3;
    const float* gx_src0 = g_gx + (size_t)sgb * NG + sgg * 1024 + hbase;
    int abb[8], akk[8], asp[8];
    #pragma unroll
    for (int v = 0; v < 8; v++) {
        const int sp = v >> 2, idx2 = tid + (v & 3) * 256;
        asp[v] = sp; abb[v] = idx2 >> 4; akk[v] = idx2 & 15;
    }

    // GX prefetch for t = 0
    float4 gxr0 = __ldcs((const float4*)gx_src0);
    float4 gxr1 = __ldcs((const float4*)(gx_src0 + 4));

    for (int t = 0; t < TT; t++) {
        const int par = t & 1;
        const __nv_bfloat16* abase = &g_abf[par][0][0][0];

        // ---- prologue staging (R11 pattern): ldg chunk0 -> STS buf0, ldg chunk1 ----
        uint4 stg[8];
        #pragma unroll
        for (int v = 0; v < 8; v++)
            stg[v] = *(const uint4*)(abase + asp[v] * 65536 + abb[v] * 1024 + akk[v] * 8);
        #pragma unroll
        for (int v = 0; v < 8; v++)
            STS128(sb + ABUFB(0, asp[v]) + abb[v] * 272 + akk[v] * 16,
                   stg[v].x, stg[v].y, stg[v].z, stg[v].w);
        #pragma unroll
        for (int v = 0; v < 8; v++)
            stg[v] = *(const uint4*)(abase + asp[v] * 65536 + abb[v] * 1024 + 128 + akk[v] * 8);
        __syncthreads();

        float Ca[2][4], Cb[2][4], Cc[2][4];   // hh, hl, lh terms
        #pragma unroll
        for (int nf = 0; nf < 2; nf++)
            #pragma unroll
            for (int e = 0; e < 4; e++) { Ca[nf][e] = 0.0f; Cb[nf][e] = 0.0f; Cc[nf][e] = 0.0f; }

        for (int i = 0; i < 8; i++) {
            // STS chunk i+1 (prev reader of that parity done at last sync)
            if (i < 7) {
                #pragma unroll
                for (int v = 0; v < 8; v++)
                    STS128(sb + ABUFB((i + 1) & 1, asp[v]) + abb[v] * 272 + akk[v] * 16,
                           stg[v].x, stg[v].y, stg[v].z, stg[v].w);
            }
            // LDG chunk i+2 — a whole compute phase of latency slack
            if (i < 6) {
                #pragma unroll
                for (int v = 0; v < 8; v++)
                    stg[v] = *(const uint4*)(abase + asp[v] * 65536 + abb[v] * 1024
                                             + (i + 2) * 128 + akk[v] * 8);
            }
            // compute chunk i on buffer i&1 (3 independent accumulator chains)
            const u32 ahB = sb + ABUFB(i & 1, 0) + a_off;
            const u32 alB = sb + ABUFB(i & 1, 1) + a_off;
            const u32 bhB = sb + OFF_WHI + b_off + i * 256;
            const u32 blB = sb + OFF_WLO + b_off + i * 256;
            #pragma unroll
            for (int k16 = 0; k16 < 8; k16++) {
                u32 ah[4], al[4], bh[4], bl[4];
                LDM4(ah, ahB + k16 * 32);
                LDM4(al, alB + k16 * 32);
                LDM4(bh, bhB + k16 * 32);
                LDM4(bl, blB + k16 * 32);
                #pragma unroll
                for (int nf = 0; nf < 2; nf++) {
                    const int o = nf * 2;
                    MMA16816(Ca[nf], ah, bh[o], bh[o + 1]);
                    MMA16816(Cb[nf], ah, bl[o], bl[o + 1]);
                    MMA16816(Cc[nf], al, bh[o], bh[o + 1]);
                }
            }
            __syncthreads();
        }

        // ---- fragments -> pre_s[b][r] (combine 3 terms); gx regs -> gx_s ----
        {
            const int g2 = lane >> 2, t2 = lane & 3;
            const int row0 = mw * 16 + g2;
            #pragma unroll
            for (int nf = 0; nf < 2; nf++) {
                const int col = nw * 16 + nf * 8 + t2 * 2;
                float2 v0, v1;
                v0.x = Ca[nf][0] + Cb[nf][0] + Cc[nf][0];
                v0.y = Ca[nf][1] + Cb[nf][1] + Cc[nf][1];
                v1.x = Ca[nf][2] + Cb[nf][2] + Cc[nf][2];
                v1.y = Ca[nf][3] + Cb[nf][3] + Cc[nf][3];
                *(float2*)&pre_s[row0 * 34 + col] = v0;
                *(float2*)&pre_s[(row0 + 8) * 34 + col] = v1;
            }
            float* dst = gx_s + sgb * 33 + sgg * 8;
            dst[0] = gxr0.x; dst[1] = gxr0.y; dst[2] = gxr0.z; dst[3] = gxr0.w;
            dst[4] = gxr1.x; dst[5] = gxr1.y; dst[6] = gxr1.z; dst[7] = gxr1.w;
        }
        __syncthreads();

        // ---- elementwise LSTM update: thread owns (b_e, h0e..h0e+1) ----
        float a1v[2], c1v[2];
        #pragma unroll
        for (int e = 0; e < 2; e++) {
            const int hh = jp * 2 + e;
            const float p0 = pre_s[b_e * 34 + hh]      + gx_s[b_e * 33 + hh];
            const float p1 = pre_s[b_e * 34 + 8 + hh]  + gx_s[b_e * 33 + 8 + hh];
            const float p2 = pre_s[b_e * 34 + 16 + hh] + gx_s[b_e * 33 + 16 + hh];
            const float p3 = pre_s[b_e * 34 + 24 + hh] + gx_s[b_e * 33 + 24 + hh];
            const float cand = tanhf(p0);
            const float gu   = sigf(p1);
            const float gf   = sigf(p2);
            const float go   = sigf(p3);
            const float cc   = gu * cand + gf * creg[e];
            creg[e] = cc;
            c1v[e] = cc;
            a1v[e] = go * tanhf(cc);
        }
        {
            float2 av; av.x = a1v[0]; av.y = a1v[1];
            *(float2*)(out + (size_t)b_e * (TT * HH) + (size_t)t * HH + h0e) = av;
            __nv_bfloat16 h0 = __float2bfloat16_rn(a1v[0]);
            __nv_bfloat16 h1 = __float2bfloat16_rn(a1v[1]);
            __nv_bfloat16 l0 = __float2bfloat16_rn(a1v[0] - __bfloat162float(h0));
            __nv_bfloat16 l1 = __float2bfloat16_rn(a1v[1] - __bfloat162float(h1));
            const int np = (t + 1) & 1;
            *(u32*)&g_abf[np][0][b_e][h0e] = pkbf2(h0, h1);
            *(u32*)&g_abf[np][1][b_e][h0e] = pkbf2(l0, l1);
            if (t == TT - 1) {
                *(float2*)(out + AF_ELEMS + (size_t)b_e * HH + h0e) = av;
                float2 cv; cv.x = c1v[0]; cv.y = c1v[1];
                *(float2*)(out + AF_ELEMS + (size_t)BB * HH + (size_t)b_e * HH + h0e) = cv;
            }
        }

        // ---- grid barrier (monotonic); GX(t+1) prefetch hides under it ----
        if (t < TT - 1) {
            gxr0 = __ldcs((const float4*)(gx_src0 + (size_t)(t + 1) * BB * NG));
            gxr1 = __ldcs((const float4*)(gx_src0 + (size_t)(t + 1) * BB * NG + 4));
            __threadfence();
            __syncthreads();
            if (tid == 0) {
                const u32 old = atomicAdd(&g_bar[t], 1u);
                const u32 target = (old & ~127u) + 128u;
                while (*(volatile u32*)&g_bar[t] < target) { }
                __threadfence();
            }
            __syncthreads();
        }
    }
}

// Launch-slot shim: placed BEFORE lstm_persist so persist is the 4th user
// launch = 6th overall (2 harness launches precede) = the one ncu captures.
__global__ void dummy_k() {}

// ---------------------------------------------------------------------------
extern "C" void kernel_launch(void* const* d_in, const int* in_sizes, int n_in,
                              void* d_out, int out_size) {
    (void)in_sizes; (void)n_in; (void)out_size;
    const float* x  = (const float*)d_in[0];
    const float* a0 = (const float*)d_in[1];
    const float* c0 = (const float*)d_in[2];
    const float* wc = (const float*)d_in[3];
    const float* wu = (const float*)d_in[4];
    const float* wf = (const float*)d_in[5];
    const float* wo = (const float*)d_in[6];
    const float* bc = (const float*)d_in[7];
    const float* bu = (const float*)d_in[8];
    const float* bf = (const float*)d_in[9];
    const float* bo = (const float*)d_in[10];
    float* out = (float*)d_out;

    static int attr_set = 0;
    if (!attr_set) {
        cudaFuncSetAttribute(lstm_persist,
                             cudaFuncAttributeMaxDynamicSharedMemorySize,
                             SMEM_BYTES);
        attr_set = 1;
    }

    // Phase 0: split fp32 -> bf16 hi/lo
    split_kernel<<<(NX4 + NW4 + 255) / 256, 256>>>(x, wc, wu, wf, wo);

    // Phase 1: HMMA x-projection (GX)
    dim3 g1(32, 256);
    gx_mma<<<g1, 256>>>(bc, bu, bf, bo);

    // ncu launch-slot shim (stream-ordered, harmless)
    dummy_k<<<1, 32>>>();

    // Phase 2: persistent tensor-core recurrence
    lstm_persist<<<NCTA, 256, SMEM_BYTES>>>(a0, c0, wc, wu, wf, wo, out);
}